// round 16
// baseline (speedup 1.0000x reference)
#include <cuda_runtime.h>
#include <cuda_fp16.h>
#include <math.h>
#include <stdint.h>

#define T_TOK 2048
#define D     1024
#define DM    4096
#define E     8
#define CAP   2048

// ---------------- device scratch (static: allocation-guard safe) ----------------
__device__ int   g_cnt[E];
__device__ int   g_tok[E * CAP];
__device__ float g_wt [E * CAP];
__device__ int   g_done[E * 16];              // per (expert,row-block) up-completion counter
__device__ __half g_xh[T_TOK * D];
__device__ __half g_hh[(size_t)E * CAP * DM]; // 128 MB

// ---------------- helpers ----------------
__device__ __forceinline__ uint32_t smem_u32(const void* p) {
    uint32_t a;
    asm("{ .reg .u64 t; cvta.to.shared.u64 t, %1; cvt.u32.u64 %0, t; }" : "=r"(a) : "l"(p));
    return a;
}
__device__ __forceinline__ uint32_t packh(float a, float b) {
    __half2 t = __floats2half2_rn(a, b);
    return *reinterpret_cast<uint32_t*>(&t);
}
__device__ __forceinline__ void cv8h(float4 a, float4 b, uint4& u) {
    u.x = packh(a.x, a.y); u.y = packh(a.z, a.w);
    u.z = packh(b.x, b.y); u.w = packh(b.z, b.w);
}
__device__ __forceinline__ float4 ldg_cg4(const float* p) {
    float4 v;
    asm volatile("ld.global.cg.v4.f32 {%0,%1,%2,%3}, [%4];"
        : "=f"(v.x), "=f"(v.y), "=f"(v.z), "=f"(v.w) : "l"(p));
    return v;
}
__device__ __forceinline__ void ldsm4(uint32_t (&r)[4], uint32_t addr) {
    asm volatile("ldmatrix.sync.aligned.m8n8.x4.shared.b16 {%0,%1,%2,%3}, [%4];"
        : "=r"(r[0]), "=r"(r[1]), "=r"(r[2]), "=r"(r[3]) : "r"(addr));
}
__device__ __forceinline__ void ldsm4t(uint32_t (&r)[4], uint32_t addr) {
    asm volatile("ldmatrix.sync.aligned.m8n8.x4.trans.shared.b16 {%0,%1,%2,%3}, [%4];"
        : "=r"(r[0]), "=r"(r[1]), "=r"(r[2]), "=r"(r[3]) : "r"(addr));
}
__device__ __forceinline__ void mma16816(float* d, const uint32_t (&a)[4],
                                         uint32_t b0, uint32_t b1) {
    asm volatile(
        "mma.sync.aligned.m16n8k16.row.col.f32.f16.f16.f32 "
        "{%0,%1,%2,%3}, {%4,%5,%6,%7}, {%8,%9}, {%0,%1,%2,%3};"
        : "+f"(d[0]), "+f"(d[1]), "+f"(d[2]), "+f"(d[3])
        : "r"(a[0]), "r"(a[1]), "r"(a[2]), "r"(a[3]), "r"(b0), "r"(b1));
}
__device__ __forceinline__ void cpa16(uint32_t s, const void* g) {
    asm volatile("cp.async.cg.shared.global [%0], [%1], 16;" :: "r"(s), "l"(g));
}
__device__ __forceinline__ void red_add_v2(float* p, float a, float b) {
    asm volatile("red.global.add.v2.f32 [%0], {%1, %2};"
        :: "l"(p), "f"(a), "f"(b) : "memory");
}
#define CP_COMMIT() asm volatile("cp.async.commit_group;" ::: "memory")
#define CP_WAIT0()  asm volatile("cp.async.wait_group 0;" ::: "memory")

// stage layout (bytes), BK=64 (R10/R15 proven best), shared by both paths:
//   A [0,18432): 128 rows x 144B (128B data + 16 pad)
//   B [18432, 18432+36864): 4 blocks x (64 k-rows x 144B) = 4 x 9216
#define STAGE   55296
#define SMEMSZ  (2 * STAGE)

#define UP_BLOCKS 4096     // 8 experts x 16 rowblks x 32 nblks
#define DN_BLOCKS 512      // 8 experts x 16 rowblks x 4 nblks

// ---------------------------------------------------------------
__global__ void zero_cnt_kernel() {
    int t = threadIdx.x;
    if (t < E) g_cnt[t] = 0;
    if (t < E * 16) g_done[t] = 0;
}

__global__ void convert_x_kernel(const float4* __restrict__ x4) {
    int i = blockIdx.x * blockDim.x + threadIdx.x;
    float4 v = x4[i];
    ((uint2*)g_xh)[i] = make_uint2(packh(v.x, v.y), packh(v.z, v.w));
}

__global__ void router_kernel(const float* __restrict__ x,
                              const float* __restrict__ Wg) {
    int t = blockIdx.x;
    int lane = threadIdx.x & 31;
    int w = threadIdx.x >> 5;
    const float* h = x + (size_t)t * D;
    float s = 0.f;
    for (int i = lane; i < D; i += 32) s += h[i] * Wg[i * E + w];
    #pragma unroll
    for (int o = 16; o; o >>= 1) s += __shfl_xor_sync(0xffffffffu, s, o);
    __shared__ float logits[E];
    if (lane == 0) logits[w] = s;
    __syncthreads();
    if (threadIdx.x == 0) {
        float m = -1e30f;
        #pragma unroll
        for (int e = 0; e < E; e++) m = fmaxf(m, logits[e]);
        float p[E];
        #pragma unroll
        for (int e = 0; e < E; e++) p[e] = expf(logits[e] - m);
        int e0 = 0;
        #pragma unroll
        for (int e = 1; e < E; e++) if (p[e] > p[e0]) e0 = e;
        int e1 = (e0 == 0) ? 1 : 0;
        #pragma unroll
        for (int e = 0; e < E; e++) { if (e == e0) continue; if (p[e] > p[e1]) e1 = e; }
        float rs = 1.f / (p[e0] + p[e1]);
        int i0 = atomicAdd(&g_cnt[e0], 1);
        g_tok[e0 * CAP + i0] = t;  g_wt[e0 * CAP + i0] = p[e0] * rs;
        int i1 = atomicAdd(&g_cnt[e1], 1);
        g_tok[e1 * CAP + i1] = t;  g_wt[e1 * CAP + i1] = p[e1] * rs;
    }
}

// ---------------------------------------------------------------
// Fused MoE kernel. CTAs [0, UP_BLOCKS): up-proj; [UP_BLOCKS, +DN_BLOCKS): down-proj.
// Bid-ordered dispatch guarantees all up CTAs are placed before any dn CTA;
// dn CTAs spin on per-(expert,rowblk) counters signalled by up CTAs.
__global__ void __launch_bounds__(512, 1)
moe_fused_kernel(const float* __restrict__ Wgate, const float* __restrict__ Win,
                 const float* __restrict__ Wout, float* __restrict__ out) {
    extern __shared__ char smem[];
    uint32_t sb = smem_u32(smem);
    int bid = blockIdx.x;
    int tid = threadIdx.x, wid = tid >> 5, lane = tid & 31;

    if (bid < UP_BLOCKS) {
        // ================= UP PATH (identical math to R15) =================
        int e = bid >> 9;
        int rem = bid & 511;
        int rowblk = rem >> 5;
        int nblk = rem & 31;
        int cnt = g_cnt[e];
        int row0 = rowblk * 128;
        int flag = e * 16 + rowblk;
        if (row0 >= cnt) {
            if (tid == 0) atomicAdd(&g_done[flag], 1);
            return;
        }
        int n0 = nblk * 128;

        int warp_m = wid >> 2, warp_n = wid & 3;   // 4 x 4

        int rA = tid >> 2, q = tid & 3;
        int tok = g_tok[e * CAP + min(row0 + rA, cnt - 1)];
        const char* gA = (const char*)(g_xh + (size_t)tok * D) + q * 32;
        uint32_t sA = rA * 144 + q * 32;

        int bk = tid >> 4, bn = (tid & 15) * 8;
        const float* pG = Wgate + (size_t)e * D * DM + (size_t)bk * DM + n0 + bn;
        const float* pI = Win   + (size_t)e * D * DM + (size_t)bk * DM + n0 + bn;
        uint32_t sB = 18432 + (uint32_t)(bn >> 6) * 9216 + bk * 144 + (bn & 63) * 2;

        uint32_t aB = sb + (warp_m * 32 + (lane & 15)) * 144 + (lane >> 4) * 16;
        uint32_t bB = sb + 18432 + (warp_n >> 1) * 9216 + (lane & 15) * 144
                    + ((warp_n & 1) * 32 + (lane >> 4) * 8) * 2;

        float acc[2][2][4][4];
        #pragma unroll
        for (int a = 0; a < 2; a++)
            #pragma unroll
            for (int b = 0; b < 2; b++)
                #pragma unroll
                for (int c = 0; c < 4; c++)
                    #pragma unroll
                    for (int d = 0; d < 4; d++) acc[a][b][c][d] = 0.f;

        const int NIT = D / 64;   // 16
        float4 vg[4], vi[4];

        #define LDW_UP(IT) do { \
            const float* _g = pG + (size_t)(IT) * 64 * DM; \
            const float* _i = pI + (size_t)(IT) * 64 * DM; \
            vg[0] = ldg_cg4(_g);            vg[1] = ldg_cg4(_g + 4); \
            vg[2] = ldg_cg4(_g + 32 * DM);  vg[3] = ldg_cg4(_g + 32 * DM + 4); \
            vi[0] = ldg_cg4(_i);            vi[1] = ldg_cg4(_i + 4); \
            vi[2] = ldg_cg4(_i + 32 * DM);  vi[3] = ldg_cg4(_i + 32 * DM + 4); \
        } while (0)

        #define STW_UP(ST) do { \
            uint4 u; \
            cv8h(vg[0], vg[1], u);  *(uint4*)(smem + (ST) + sB)                 = u; \
            cv8h(vg[2], vg[3], u);  *(uint4*)(smem + (ST) + sB + 4608)          = u; \
            cv8h(vi[0], vi[1], u);  *(uint4*)(smem + (ST) + sB + 18432)         = u; \
            cv8h(vi[2], vi[3], u);  *(uint4*)(smem + (ST) + sB + 18432 + 4608)  = u; \
        } while (0)

        #define CPA_U(ST, IT) do { \
            const char* _a = gA + (size_t)(IT) * 128; \
            cpa16(sb + (ST) + sA, _a); \
            cpa16(sb + (ST) + sA + 16, _a + 16); \
        } while (0)

        LDW_UP(0); STW_UP(0); CPA_U(0, 0); CP_COMMIT();
        LDW_UP(1);
        CP_WAIT0();
        __syncthreads();

        for (int it = 0; it < NIT; ++it) {
            uint32_t ps = (uint32_t)(it & 1) * STAGE;
            uint32_t qs = STAGE - ps;
            bool m1 = (it + 1 < NIT);
            if (m1) { STW_UP(qs); CPA_U(qs, it + 1); }
            CP_COMMIT();
            if (it + 2 < NIT) LDW_UP(it + 2);

            #pragma unroll
            for (int kk = 0; kk < 4; kk++) {
                uint32_t A[2][4];
                #pragma unroll
                for (int f = 0; f < 2; f++)
                    ldsm4(A[f], aB + ps + f * 2304 + kk * 32);
                #pragma unroll
                for (int mat = 0; mat < 2; mat++) {
                    uint32_t sec = ps + mat * 18432 + kk * 2304;
                    #pragma unroll
                    for (int jt = 0; jt < 2; jt++) {
                        uint32_t bh[4];
                        ldsm4t(bh, bB + sec + jt * 32);
                        #pragma unroll
                        for (int f = 0; f < 2; f++) {
                            mma16816(acc[mat][f][2*jt],   A[f], bh[0], bh[1]);
                            mma16816(acc[mat][f][2*jt+1], A[f], bh[2], bh[3]);
                        }
                    }
                }
            }
            if (m1) CP_WAIT0();
            __syncthreads();
        }

        #pragma unroll
        for (int f = 0; f < 2; f++) {
            #pragma unroll
            for (int h = 0; h < 2; h++) {
                int r = row0 + warp_m * 32 + f * 16 + (lane >> 2) + h * 8;
                if (r >= cnt) continue;
                float wt = g_wt[e * CAP + r];
                size_t base = (size_t)(e * CAP + r) * DM;
                int col = n0 + warp_n * 32 + (lane & 3) * 2;
                #pragma unroll
                for (int n8 = 0; n8 < 4; n8++) {
                    float g0 = acc[0][f][n8][2*h], g1 = acc[0][f][n8][2*h+1];
                    float i0 = acc[1][f][n8][2*h], i1 = acc[1][f][n8][2*h+1];
                    float v0 = wt * (g0 / (1.f + __expf(-g0)) * i0);
                    float v1 = wt * (g1 / (1.f + __expf(-g1)) * i1);
                    *(uint32_t*)(g_hh + base + col + n8 * 8) = packh(v0, v1);
                }
            }
        }
        // signal completion of this (expert,rowblk) n-slice
        __threadfence();
        __syncthreads();
        if (tid == 0) atomicAdd(&g_done[flag], 1);
        #undef LDW_UP
        #undef STW_UP
        #undef CPA_U

    } else {
        // ================= DN PATH (identical math to R15) =================
        int v = bid - UP_BLOCKS;
        int e = v >> 6;
        int rem = v & 63;
        int rowblk = rem >> 2;
        int nblk = rem & 3;
        int cnt = g_cnt[e];
        int row0 = rowblk * 128;
        if (row0 >= cnt) return;
        int n0 = nblk * 256;

        // wait for all 32 up n-slices of this (expert,rowblk)
        if (tid == 0) {
            while (atomicAdd(&g_done[e * 16 + rowblk], 0) < 32) __nanosleep(128);
        }
        __syncthreads();
        __threadfence();

        int warp_m = wid >> 2, warp_n = wid & 3;

        int rA = tid >> 2, q = tid & 3;
        int rowc = min(row0 + rA, cnt - 1);
        const char* gA = (const char*)(g_hh + (size_t)(e * CAP + rowc) * DM) + q * 32;
        uint32_t sA = rA * 144 + q * 32;

        int bk = tid >> 4, bn = (tid & 15) * 16;
        const float* pB = Wout + (size_t)e * DM * D + (size_t)bk * D + n0 + bn;
        uint32_t sB = 18432 + (uint32_t)(bn >> 6) * 9216 + bk * 144 + (bn & 63) * 2;

        uint32_t aB = sb + (warp_m * 32 + (lane & 15)) * 144 + (lane >> 4) * 16;
        uint32_t bB = sb + 18432 + warp_n * 9216 + (lane & 15) * 144 + (lane >> 4) * 16;

        float acc[2][8][4];
        #pragma unroll
        for (int a = 0; a < 2; a++)
            #pragma unroll
            for (int b = 0; b < 8; b++)
                #pragma unroll
                for (int c = 0; c < 4; c++) acc[a][b][c] = 0.f;

        const int NIT = DM / 64;   // 64
        float4 vb0, vb1, vb2, vb3, vb4, vb5, vb6, vb7;

        #define LDW_DN(IT) do { \
            const float* _w = pB + (size_t)(IT) * 64 * D; \
            vb0 = ldg_cg4(_w);           vb1 = ldg_cg4(_w + 4); \
            vb2 = ldg_cg4(_w + 8);       vb3 = ldg_cg4(_w + 12); \
            vb4 = ldg_cg4(_w + 32 * D);      vb5 = ldg_cg4(_w + 32 * D + 4); \
            vb6 = ldg_cg4(_w + 32 * D + 8);  vb7 = ldg_cg4(_w + 32 * D + 12); \
        } while (0)

        #define STW_DN(ST) do { \
            uint4 u; \
            cv8h(vb0, vb1, u);  *(uint4*)(smem + (ST) + sB)              = u; \
            cv8h(vb2, vb3, u);  *(uint4*)(smem + (ST) + sB + 16)         = u; \
            cv8h(vb4, vb5, u);  *(uint4*)(smem + (ST) + sB + 4608)       = u; \
            cv8h(vb6, vb7, u);  *(uint4*)(smem + (ST) + sB + 4608 + 16)  = u; \
        } while (0)

        #define CPA_D(ST, IT) do { \
            const char* _a = gA + (size_t)(IT) * 128; \
            cpa16(sb + (ST) + sA, _a); \
            cpa16(sb + (ST) + sA + 16, _a + 16); \
        } while (0)

        LDW_DN(0); STW_DN(0); CPA_D(0, 0); CP_COMMIT();
        LDW_DN(1);
        CP_WAIT0();
        __syncthreads();

        for (int it = 0; it < NIT; ++it) {
            uint32_t ps = (uint32_t)(it & 1) * STAGE;
            uint32_t qs = STAGE - ps;
            bool m1 = (it + 1 < NIT);
            if (m1) { STW_DN(qs); CPA_D(qs, it + 1); }
            CP_COMMIT();
            if (it + 2 < NIT) LDW_DN(it + 2);

            #pragma unroll
            for (int kk = 0; kk < 4; kk++) {
                uint32_t A[2][4];
                #pragma unroll
                for (int f = 0; f < 2; f++)
                    ldsm4(A[f], aB + ps + f * 2304 + kk * 32);
                #pragma unroll
                for (int jt = 0; jt < 4; jt++) {
                    uint32_t bh[4];
                    ldsm4t(bh, bB + ps + kk * 2304 + jt * 32);
                    #pragma unroll
                    for (int f = 0; f < 2; f++) {
                        mma16816(acc[f][2*jt],   A[f], bh[0], bh[1]);
                        mma16816(acc[f][2*jt+1], A[f], bh[2], bh[3]);
                    }
                }
            }
            if (m1) CP_WAIT0();
            __syncthreads();
        }

        #pragma unroll
        for (int f = 0; f < 2; f++) {
            #pragma unroll
            for (int h = 0; h < 2; h++) {
                int r = row0 + warp_m * 32 + f * 16 + (lane >> 2) + h * 8;
                if (r >= cnt) continue;
                int tk = g_tok[e * CAP + r];
                float* po = out + (size_t)tk * D + n0 + warp_n * 64 + (lane & 3) * 2;
                #pragma unroll
                for (int n8 = 0; n8 < 8; n8++)
                    red_add_v2(po + n8 * 8, acc[f][n8][2*h], acc[f][n8][2*h + 1]);
            }
        }
        #undef LDW_DN
        #undef STW_DN
        #undef CPA_D
    }
}

// ---------------------------------------------------------------
extern "C" void kernel_launch(void* const* d_in, const int* in_sizes, int n_in,
                              void* d_out, int out_size) {
    const float* x   = (const float*)d_in[0];
    const float* Wg  = (const float*)d_in[1];
    const float* Weg = (const float*)d_in[2];
    const float* Wei = (const float*)d_in[3];
    const float* Weo = (const float*)d_in[4];
    float* out = (float*)d_out;

    static int attr_set = 0;
    if (!attr_set) {
        cudaFuncSetAttribute(moe_fused_kernel, cudaFuncAttributeMaxDynamicSharedMemorySize, SMEMSZ);
        attr_set = 1;
    }

    cudaMemsetAsync(out, 0, (size_t)out_size * sizeof(float));
    zero_cnt_kernel<<<1, 160>>>();
    convert_x_kernel<<<(T_TOK * D / 4) / 256, 256>>>((const float4*)x);
    router_kernel<<<T_TOK, 256>>>(x, Wg);
    moe_fused_kernel<<<UP_BLOCKS + DN_BLOCKS, 512, SMEMSZ>>>(Weg, Wei, Weo, out);
}

// round 17
// speedup vs baseline: 1.0460x; 1.0460x over previous
#include <cuda_runtime.h>
#include <cuda_fp16.h>
#include <math.h>
#include <stdint.h>

#define T_TOK 2048
#define D     1024
#define DM    4096
#define E     8
#define CAP   2048

// ---------------- device scratch (static: allocation-guard safe) ----------------
__device__ int   g_cnt[E];
__device__ int   g_tok[E * CAP];
__device__ float g_wt [E * CAP];
__device__ __half g_xh[T_TOK * D];
__device__ __half g_hh[(size_t)E * CAP * DM];   // 128 MB

// ---------------- helpers ----------------
__device__ __forceinline__ uint32_t smem_u32(const void* p) {
    uint32_t a;
    asm("{ .reg .u64 t; cvta.to.shared.u64 t, %1; cvt.u32.u64 %0, t; }" : "=r"(a) : "l"(p));
    return a;
}
__device__ __forceinline__ uint32_t packh(float a, float b) {
    __half2 t = __floats2half2_rn(a, b);
    return *reinterpret_cast<uint32_t*>(&t);
}
__device__ __forceinline__ void cv8h(float4 a, float4 b, uint4& u) {
    u.x = packh(a.x, a.y); u.y = packh(a.z, a.w);
    u.z = packh(b.x, b.y); u.w = packh(b.z, b.w);
}
__device__ __forceinline__ float4 ldg_cg4(const float* p) {
    float4 v;
    asm volatile("ld.global.cg.v4.f32 {%0,%1,%2,%3}, [%4];"
        : "=f"(v.x), "=f"(v.y), "=f"(v.z), "=f"(v.w) : "l"(p));
    return v;
}
__device__ __forceinline__ void ldsm4(uint32_t (&r)[4], uint32_t addr) {
    asm volatile("ldmatrix.sync.aligned.m8n8.x4.shared.b16 {%0,%1,%2,%3}, [%4];"
        : "=r"(r[0]), "=r"(r[1]), "=r"(r[2]), "=r"(r[3]) : "r"(addr));
}
__device__ __forceinline__ void ldsm4t(uint32_t (&r)[4], uint32_t addr) {
    asm volatile("ldmatrix.sync.aligned.m8n8.x4.trans.shared.b16 {%0,%1,%2,%3}, [%4];"
        : "=r"(r[0]), "=r"(r[1]), "=r"(r[2]), "=r"(r[3]) : "r"(addr));
}
__device__ __forceinline__ void mma16816(float* d, const uint32_t (&a)[4],
                                         uint32_t b0, uint32_t b1) {
    asm volatile(
        "mma.sync.aligned.m16n8k16.row.col.f32.f16.f16.f32 "
        "{%0,%1,%2,%3}, {%4,%5,%6,%7}, {%8,%9}, {%0,%1,%2,%3};"
        : "+f"(d[0]), "+f"(d[1]), "+f"(d[2]), "+f"(d[3])
        : "r"(a[0]), "r"(a[1]), "r"(a[2]), "r"(a[3]), "r"(b0), "r"(b1));
}
__device__ __forceinline__ void cpa16(uint32_t s, const void* g) {
    asm volatile("cp.async.cg.shared.global [%0], [%1], 16;" :: "r"(s), "l"(g));
}
__device__ __forceinline__ void red_add_v2(float* p, float a, float b) {
    asm volatile("red.global.add.v2.f32 [%0], {%1, %2};"
        :: "l"(p), "f"(a), "f"(b) : "memory");
}
#define CP_COMMIT() asm volatile("cp.async.commit_group;" ::: "memory")
#define CP_WAIT0()  asm volatile("cp.async.wait_group 0;" ::: "memory")

// stage layout (bytes), BK=64 (R10/R15 proven best):
//   A [0,18432): 128 rows x 144B (128B data + 16 pad)
//   B [18432, 18432+36864): 4 blocks x (64 k-rows x 144B) = 4 x 9216
#define STAGE   55296
#define SMEMSZ  (2 * STAGE)

// ---------------------------------------------------------------
__global__ void zero_cnt_kernel() {
    if (threadIdx.x < E) g_cnt[threadIdx.x] = 0;
}

// Fused router + x conversion: one block per token.
// Warps 0..7 compute the 8 expert logits; then all 256 threads convert the
// token's 1024 fp32 -> fp16 into g_xh (single pass over x).
__global__ void router_kernel(const float* __restrict__ x,
                              const float* __restrict__ Wg) {
    int t = blockIdx.x;
    int lane = threadIdx.x & 31;
    int w = threadIdx.x >> 5;
    const float* h = x + (size_t)t * D;

    float s = 0.f;
    for (int i = lane; i < D; i += 32) s += h[i] * Wg[i * E + w];
    #pragma unroll
    for (int o = 16; o; o >>= 1) s += __shfl_xor_sync(0xffffffffu, s, o);
    __shared__ float logits[E];
    if (lane == 0) logits[w] = s;

    // convert this token's row to fp16 (4 floats per thread)
    {
        int i = threadIdx.x;            // 0..255
        float4 v = *(const float4*)(h + i * 4);
        ((uint2*)(g_xh + (size_t)t * D))[i] =
            make_uint2(packh(v.x, v.y), packh(v.z, v.w));
    }

    __syncthreads();
    if (threadIdx.x == 0) {
        float m = -1e30f;
        #pragma unroll
        for (int e = 0; e < E; e++) m = fmaxf(m, logits[e]);
        float p[E];
        #pragma unroll
        for (int e = 0; e < E; e++) p[e] = expf(logits[e] - m);
        int e0 = 0;
        #pragma unroll
        for (int e = 1; e < E; e++) if (p[e] > p[e0]) e0 = e;
        int e1 = (e0 == 0) ? 1 : 0;
        #pragma unroll
        for (int e = 0; e < E; e++) { if (e == e0) continue; if (p[e] > p[e1]) e1 = e; }
        float rs = 1.f / (p[e0] + p[e1]);
        int i0 = atomicAdd(&g_cnt[e0], 1);
        g_tok[e0 * CAP + i0] = t;  g_wt[e0 * CAP + i0] = p[e0] * rs;
        int i1 = atomicAdd(&g_cnt[e1], 1);
        g_tok[e1 * CAP + i1] = t;  g_wt[e1 * CAP + i1] = p[e1] * rs;
    }
}

// ---------------------------------------------------------------
// Up-proj: M128 x N128 (G and I each), 16 warps, warp tile m32 x n32 (both mats).
// fp16 single-product, fp32 accumulate, BK=64. wt folded into hid output.
// (identical to R15 best)
__global__ void __launch_bounds__(512, 1)
moe_up_kernel(const float* __restrict__ Wgate, const float* __restrict__ Win) {
    extern __shared__ char smem[];
    uint32_t sb = smem_u32(smem);

    int e = blockIdx.z;
    int cnt = g_cnt[e];
    int row0 = blockIdx.x * 128;
    if (row0 >= cnt) return;
    int n0 = blockIdx.y * 128;

    int tid = threadIdx.x, wid = tid >> 5, lane = tid & 31;
    int warp_m = wid >> 2, warp_n = wid & 3;   // 4 x 4

    int rA = tid >> 2, q = tid & 3;
    int tok = g_tok[e * CAP + min(row0 + rA, cnt - 1)];
    const char* gA = (const char*)(g_xh + (size_t)tok * D) + q * 32;
    uint32_t sA = rA * 144 + q * 32;

    int bk = tid >> 4, bn = (tid & 15) * 8;
    const float* pG = Wgate + (size_t)e * D * DM + (size_t)bk * DM + n0 + bn;
    const float* pI = Win   + (size_t)e * D * DM + (size_t)bk * DM + n0 + bn;
    uint32_t sB = 18432 + (uint32_t)(bn >> 6) * 9216 + bk * 144 + (bn & 63) * 2;

    uint32_t aB = sb + (warp_m * 32 + (lane & 15)) * 144 + (lane >> 4) * 16;
    uint32_t bB = sb + 18432 + (warp_n >> 1) * 9216 + (lane & 15) * 144
                + ((warp_n & 1) * 32 + (lane >> 4) * 8) * 2;

    float acc[2][2][4][4];
    #pragma unroll
    for (int a = 0; a < 2; a++)
        #pragma unroll
        for (int b = 0; b < 2; b++)
            #pragma unroll
            for (int c = 0; c < 4; c++)
                #pragma unroll
                for (int d = 0; d < 4; d++) acc[a][b][c][d] = 0.f;

    const int NIT = D / 64;   // 16
    float4 vg[4], vi[4];

    #define LDW_UP(IT) do { \
        const float* _g = pG + (size_t)(IT) * 64 * DM; \
        const float* _i = pI + (size_t)(IT) * 64 * DM; \
        vg[0] = ldg_cg4(_g);            vg[1] = ldg_cg4(_g + 4); \
        vg[2] = ldg_cg4(_g + 32 * DM);  vg[3] = ldg_cg4(_g + 32 * DM + 4); \
        vi[0] = ldg_cg4(_i);            vi[1] = ldg_cg4(_i + 4); \
        vi[2] = ldg_cg4(_i + 32 * DM);  vi[3] = ldg_cg4(_i + 32 * DM + 4); \
    } while (0)

    #define STW_UP(ST) do { \
        uint4 u; \
        cv8h(vg[0], vg[1], u);  *(uint4*)(smem + (ST) + sB)                 = u; \
        cv8h(vg[2], vg[3], u);  *(uint4*)(smem + (ST) + sB + 4608)          = u; \
        cv8h(vi[0], vi[1], u);  *(uint4*)(smem + (ST) + sB + 18432)         = u; \
        cv8h(vi[2], vi[3], u);  *(uint4*)(smem + (ST) + sB + 18432 + 4608)  = u; \
    } while (0)

    #define CPA_T(ST, IT) do { \
        const char* _a = gA + (size_t)(IT) * 128; \
        cpa16(sb + (ST) + sA, _a); \
        cpa16(sb + (ST) + sA + 16, _a + 16); \
    } while (0)

    LDW_UP(0); STW_UP(0); CPA_T(0, 0); CP_COMMIT();
    LDW_UP(1);
    CP_WAIT0();
    __syncthreads();

    for (int it = 0; it < NIT; ++it) {
        uint32_t ps = (uint32_t)(it & 1) * STAGE;
        uint32_t qs = STAGE - ps;
        bool m1 = (it + 1 < NIT);
        if (m1) { STW_UP(qs); CPA_T(qs, it + 1); }
        CP_COMMIT();
        if (it + 2 < NIT) LDW_UP(it + 2);

        #pragma unroll
        for (int kk = 0; kk < 4; kk++) {
            uint32_t A[2][4];
            #pragma unroll
            for (int f = 0; f < 2; f++)
                ldsm4(A[f], aB + ps + f * 2304 + kk * 32);
            #pragma unroll
            for (int mat = 0; mat < 2; mat++) {
                uint32_t sec = ps + mat * 18432 + kk * 2304;
                #pragma unroll
                for (int jt = 0; jt < 2; jt++) {
                    uint32_t bh[4];
                    ldsm4t(bh, bB + sec + jt * 32);
                    #pragma unroll
                    for (int f = 0; f < 2; f++) {
                        mma16816(acc[mat][f][2*jt],   A[f], bh[0], bh[1]);
                        mma16816(acc[mat][f][2*jt+1], A[f], bh[2], bh[3]);
                    }
                }
            }
        }
        if (m1) CP_WAIT0();
        __syncthreads();
    }

    #pragma unroll
    for (int f = 0; f < 2; f++) {
        #pragma unroll
        for (int h = 0; h < 2; h++) {
            int r = row0 + warp_m * 32 + f * 16 + (lane >> 2) + h * 8;
            if (r >= cnt) continue;
            float wt = g_wt[e * CAP + r];
            size_t base = (size_t)(e * CAP + r) * DM;
            int col = n0 + warp_n * 32 + (lane & 3) * 2;
            #pragma unroll
            for (int n8 = 0; n8 < 4; n8++) {
                float g0 = acc[0][f][n8][2*h], g1 = acc[0][f][n8][2*h+1];
                float i0 = acc[1][f][n8][2*h], i1 = acc[1][f][n8][2*h+1];
                float v0 = wt * (g0 / (1.f + __expf(-g0)) * i0);
                float v1 = wt * (g1 / (1.f + __expf(-g1)) * i1);
                *(uint32_t*)(g_hh + base + col + n8 * 8) = packh(v0, v1);
            }
        }
    }
    #undef LDW_UP
    #undef STW_UP
    #undef CPA_T
}

// ---------------------------------------------------------------
// Down-proj + scatter: M128 x N256 tile, 16 warps, warp m32 x n64, BK=64.
// (identical to R15 best; red.global.add.v2.f32 epilogue)
__global__ void __launch_bounds__(512, 1)
moe_dn_kernel(const float* __restrict__ Wout, float* __restrict__ out) {
    extern __shared__ char smem[];
    uint32_t sb = smem_u32(smem);

    int e = blockIdx.z;
    int cnt = g_cnt[e];
    int row0 = blockIdx.x * 128;
    if (row0 >= cnt) return;
    int n0 = blockIdx.y * 256;

    int tid = threadIdx.x, wid = tid >> 5, lane = tid & 31;
    int warp_m = wid >> 2, warp_n = wid & 3;

    int rA = tid >> 2, q = tid & 3;
    int rowc = min(row0 + rA, cnt - 1);
    const char* gA = (const char*)(g_hh + (size_t)(e * CAP + rowc) * DM) + q * 32;
    uint32_t sA = rA * 144 + q * 32;

    int bk = tid >> 4, bn = (tid & 15) * 16;
    const float* pB = Wout + (size_t)e * DM * D + (size_t)bk * D + n0 + bn;
    uint32_t sB = 18432 + (uint32_t)(bn >> 6) * 9216 + bk * 144 + (bn & 63) * 2;

    uint32_t aB = sb + (warp_m * 32 + (lane & 15)) * 144 + (lane >> 4) * 16;
    uint32_t bB = sb + 18432 + warp_n * 9216 + (lane & 15) * 144 + (lane >> 4) * 16;

    float acc[2][8][4];
    #pragma unroll
    for (int a = 0; a < 2; a++)
        #pragma unroll
        for (int b = 0; b < 8; b++)
            #pragma unroll
            for (int c = 0; c < 4; c++) acc[a][b][c] = 0.f;

    const int NIT = DM / 64;   // 64
    float4 vb0, vb1, vb2, vb3, vb4, vb5, vb6, vb7;

    #define LDW_DN(IT) do { \
        const float* _w = pB + (size_t)(IT) * 64 * D; \
        vb0 = ldg_cg4(_w);           vb1 = ldg_cg4(_w + 4); \
        vb2 = ldg_cg4(_w + 8);       vb3 = ldg_cg4(_w + 12); \
        vb4 = ldg_cg4(_w + 32 * D);      vb5 = ldg_cg4(_w + 32 * D + 4); \
        vb6 = ldg_cg4(_w + 32 * D + 8);  vb7 = ldg_cg4(_w + 32 * D + 12); \
    } while (0)

    #define STW_DN(ST) do { \
        uint4 u; \
        cv8h(vb0, vb1, u);  *(uint4*)(smem + (ST) + sB)              = u; \
        cv8h(vb2, vb3, u);  *(uint4*)(smem + (ST) + sB + 16)         = u; \
        cv8h(vb4, vb5, u);  *(uint4*)(smem + (ST) + sB + 4608)       = u; \
        cv8h(vb6, vb7, u);  *(uint4*)(smem + (ST) + sB + 4608 + 16)  = u; \
    } while (0)

    #define CPA_T(ST, IT) do { \
        const char* _a = gA + (size_t)(IT) * 128; \
        cpa16(sb + (ST) + sA, _a); \
        cpa16(sb + (ST) + sA + 16, _a + 16); \
    } while (0)

    LDW_DN(0); STW_DN(0); CPA_T(0, 0); CP_COMMIT();
    LDW_DN(1);
    CP_WAIT0();
    __syncthreads();

    for (int it = 0; it < NIT; ++it) {
        uint32_t ps = (uint32_t)(it & 1) * STAGE;
        uint32_t qs = STAGE - ps;
        bool m1 = (it + 1 < NIT);
        if (m1) { STW_DN(qs); CPA_T(qs, it + 1); }
        CP_COMMIT();
        if (it + 2 < NIT) LDW_DN(it + 2);

        #pragma unroll
        for (int kk = 0; kk < 4; kk++) {
            uint32_t A[2][4];
            #pragma unroll
            for (int f = 0; f < 2; f++)
                ldsm4(A[f], aB + ps + f * 2304 + kk * 32);
            #pragma unroll
            for (int jt = 0; jt < 4; jt++) {
                uint32_t bh[4];
                ldsm4t(bh, bB + ps + kk * 2304 + jt * 32);
                #pragma unroll
                for (int f = 0; f < 2; f++) {
                    mma16816(acc[f][2*jt],   A[f], bh[0], bh[1]);
                    mma16816(acc[f][2*jt+1], A[f], bh[2], bh[3]);
                }
            }
        }
        if (m1) CP_WAIT0();
        __syncthreads();
    }

    #pragma unroll
    for (int f = 0; f < 2; f++) {
        #pragma unroll
        for (int h = 0; h < 2; h++) {
            int r = row0 + warp_m * 32 + f * 16 + (lane >> 2) + h * 8;
            if (r >= cnt) continue;
            int tk = g_tok[e * CAP + r];
            float* po = out + (size_t)tk * D + n0 + warp_n * 64 + (lane & 3) * 2;
            #pragma unroll
            for (int n8 = 0; n8 < 8; n8++)
                red_add_v2(po + n8 * 8, acc[f][n8][2*h], acc[f][n8][2*h + 1]);
        }
    }
    #undef LDW_DN
    #undef STW_DN
    #undef CPA_T
}

// ---------------------------------------------------------------
extern "C" void kernel_launch(void* const* d_in, const int* in_sizes, int n_in,
                              void* d_out, int out_size) {
    const float* x   = (const float*)d_in[0];
    const float* Wg  = (const float*)d_in[1];
    const float* Weg = (const float*)d_in[2];
    const float* Wei = (const float*)d_in[3];
    const float* Weo = (const float*)d_in[4];
    float* out = (float*)d_out;

    static int attr_set = 0;
    if (!attr_set) {
        cudaFuncSetAttribute(moe_up_kernel, cudaFuncAttributeMaxDynamicSharedMemorySize, SMEMSZ);
        cudaFuncSetAttribute(moe_dn_kernel, cudaFuncAttributeMaxDynamicSharedMemorySize, SMEMSZ);
        attr_set = 1;
    }

    cudaMemsetAsync(out, 0, (size_t)out_size * sizeof(float));
    zero_cnt_kernel<<<1, 32>>>();
    router_kernel<<<T_TOK, 256>>>(x, Wg);
    moe_up_kernel<<<dim3(CAP / 128, DM / 128, E), 512, SMEMSZ>>>(Weg, Wei);
    moe_dn_kernel<<<dim3(CAP / 128, D / 256, E), 512, SMEMSZ>>>(Weo, out);
}